// round 5
// baseline (speedup 1.0000x reference)
#include <cuda_runtime.h>
#include <math.h>

// Problem constants
#define R_    2048
#define C_    1024
#define NCH   8

#define RPB      16               // rows per fused block
#define NBLK     (R_ / RPB)       // 128  (# of Lpart k-partials)
#define NB3      128              // K3 grid

// Scratch (no allocations allowed -> device globals)
__device__ float g_Lpart[NBLK * NCH * C_];   // partial log-sums per row-block (4MB)
__device__ float g_pA[64 * NBLK];            // [col64][block128] sum_r P*s
__device__ float g_pB[64 * NBLK];            // [col64][block128] sum_r P
__device__ float g_pSel[NBLK];               // per-block partial row-sel count
__device__ float g_nnz[64];                  // reduced nnz_ch_ba
__device__ float g_psum[64];                 // reduced sum_r P per (ch,ba)
__device__ float g_ncolPart[NB3];            // per-K3-block colch sums
__device__ float g_selv;                     // reduced row-sel count
__device__ unsigned int g_count = 0;         // K3 completion ticket (self-resetting)

// ---------------------------------------------------------------------------
// KF (fused): 512 threads, each block owns 16 rows.
//  Stage A: 16 warps x 1 row -> softmax over 64, write P, stage P/lq/sel in smem.
//  Stage B: stream the 16x1024 D tile once; each thread owns 2 columns (float2),
//           16 accumulators, per-row sums in registers.
//  Stage C: write Lpart + per-block pA/pB/sel partials.
// ---------------------------------------------------------------------------
__global__ __launch_bounds__(512) void kf_fused(const float* __restrict__ W,
                                                const float* __restrict__ D,
                                                const float* __restrict__ G,
                                                float* __restrict__ outP)
{
    __shared__ float sP[RPB][64];
    __shared__ float slq[RPB][NCH];
    __shared__ float sds[RPB][16];
    __shared__ float sSel[RPB];
    __shared__ float sS[RPB];

    const int t    = threadIdx.x;
    const int wid  = t >> 5;          // 0..15
    const int lane = t & 31;
    const int r0   = blockIdx.x * RPB;

    const float2* W2 = reinterpret_cast<const float2*>(W);
    const float2* G2 = reinterpret_cast<const float2*>(G);

    // ---- Stage A: one row per warp ----
    {
        const int rl = wid;
        const int r  = r0 + rl;

        float2 w  = W2[r * 32 + lane];
        float2 gv = G2[r * 32 + lane];
        float e0 = w.x + gv.x;
        float e1 = w.y + gv.y;

        float m = fmaxf(e0, e1);
        #pragma unroll
        for (int o = 16; o > 0; o >>= 1)
            m = fmaxf(m, __shfl_xor_sync(0xFFFFFFFFu, m, o));

        float x0 = expf(e0 - m);
        float x1 = expf(e1 - m);
        float s  = x0 + x1;
        #pragma unroll
        for (int o = 16; o > 0; o >>= 1)
            s += __shfl_xor_sync(0xFFFFFFFFu, s, o);

        const float inv = 1.0f / s;      // == max(P): exp(0)=1 at the argmax
        const float p0  = x0 * inv;
        const float p1  = x1 * inv;

        reinterpret_cast<float2*>(outP)[r * 32 + lane] = make_float2(p0, p1);
        sP[rl][2 * lane]     = p0;
        sP[rl][2 * lane + 1] = p1;

        float lq = log1pf(-p0) + log1pf(-p1);
        lq += __shfl_xor_sync(0xFFFFFFFFu, lq, 1);
        lq += __shfl_xor_sync(0xFFFFFFFFu, lq, 2);
        if ((lane & 3) == 0) slq[rl][lane >> 2] = lq;
        if (lane == 0) sSel[rl] = (inv > 0.99f) ? 1.0f : 0.0f;
    }
    __syncthreads();

    // ---- Stage B: single pass over the D tile; 2 cols per thread ----
    float accx[NCH], accy[NCH];
    #pragma unroll
    for (int ch = 0; ch < NCH; ch++) { accx[ch] = 0.f; accy[ch] = 0.f; }
    float dsv[RPB];

    const float2* D2 = reinterpret_cast<const float2*>(D);
    #pragma unroll
    for (int rl = 0; rl < RPB; rl++) {
        float2 d = D2[(size_t)(r0 + rl) * 512 + t];
        dsv[rl] = d.x + d.y;
        #pragma unroll
        for (int ch = 0; ch < NCH; ch++) {
            float l = slq[rl][ch];
            accx[ch] = fmaf(d.x, l, accx[ch]);
            accy[ch] = fmaf(d.y, l, accy[ch]);
        }
    }

    // per-row sums: warp-reduce after the memory loop
    #pragma unroll
    for (int rl = 0; rl < RPB; rl++) {
        float v = dsv[rl];
        #pragma unroll
        for (int o = 16; o > 0; o >>= 1)
            v += __shfl_xor_sync(0xFFFFFFFFu, v, o);
        if (lane == 0) sds[rl][wid] = v;
    }

    // ---- Stage C: write partials ----
    #pragma unroll
    for (int ch = 0; ch < NCH; ch++) {
        *reinterpret_cast<float2*>(
            &g_Lpart[((size_t)blockIdx.x * NCH + ch) * C_ + 2 * t]) =
            make_float2(accx[ch], accy[ch]);
    }
    __syncthreads();

    if (t < RPB) {
        float v = 0.f;
        #pragma unroll
        for (int w2 = 0; w2 < 16; w2++) v += sds[t][w2];
        sS[t] = v;
    }
    __syncthreads();

    if (t < 64) {
        float a = 0.f, b = 0.f;
        #pragma unroll
        for (int rl = 0; rl < RPB; rl++) {
            float p = sP[rl][t];
            b += p;
            a  = fmaf(p, sS[rl], a);
        }
        g_pA[t * NBLK + blockIdx.x] = a;     // [64][128], coalesced in K3
        g_pB[t * NBLK + blockIdx.x] = b;
    }
    if (t == 0) {
        float v = 0.f;
        #pragma unroll
        for (int rl = 0; rl < RPB; rl++) v += sSel[rl];
        g_pSel[blockIdx.x] = v;
    }
}

// ---------------------------------------------------------------------------
// K3: grid 128 x 1024 threads. Block b owns 64 outputs (one channel slice).
// 16 k-groups x 64 outputs; each thread sums 8 of the 128 partials (coalesced,
// fully unrolled). Warps 4/5/6 reduce pA/pB/sel. Last block finalizes.
// Output layout (float32, concatenated tuple):
//   P[131072] | tot[8] | max_nnz[8] | num_col[8] | num_row[8] |
//   nnz_ch_ba[64] | col_density[8] | num_row_sel[1]
// ---------------------------------------------------------------------------
__global__ __launch_bounds__(1024) void k3_reduce_final(float* __restrict__ out)
{
    const int b    = blockIdx.x;
    const int t    = threadIdx.x;
    const int lane = t & 31;
    const int wid  = t >> 5;          // 0..31
    const int ol   = t & 63;          // output within block
    const int kg   = t >> 6;          // 0..15
    const int o    = b * 64 + ol;

    // ---- each thread sums 8 partials, all loads independent ----
    const float* base = g_Lpart + (size_t)(kg * 8) * (NCH * C_) + o;
    float a0 = base[0 * (NCH * C_)];
    float a1 = base[1 * (NCH * C_)];
    float a2 = base[2 * (NCH * C_)];
    float a3 = base[3 * (NCH * C_)];
    float a4 = base[4 * (NCH * C_)];
    float a5 = base[5 * (NCH * C_)];
    float a6 = base[6 * (NCH * C_)];
    float a7 = base[7 * (NCH * C_)];
    __shared__ float red[16][64];
    red[kg][ol] = ((a0 + a1) + (a2 + a3)) + ((a4 + a5) + (a6 + a7));
    __syncthreads();

    // ---- warps 0-1: combine k-groups, colch = 1-exp, sum the 64 outputs ----
    __shared__ float cs[2];
    if (t < 64) {
        float L = 0.f;
        #pragma unroll
        for (int k = 0; k < 16; k++) L += red[k][t];
        float colch = 1.0f - expf(L);
        #pragma unroll
        for (int off = 16; off > 0; off >>= 1)
            colch += __shfl_xor_sync(0xFFFFFFFFu, colch, off);
        if (lane == 0) cs[t >> 5] = colch;
    }

    // ---- warps 4/5/6: reduce KF partials ----
    if (wid == 4 && b < 64) {                 // pA row b -> g_nnz[b]
        float a = g_pA[b * NBLK + lane]      + g_pA[b * NBLK + lane + 32]
                + g_pA[b * NBLK + lane + 64] + g_pA[b * NBLK + lane + 96];
        #pragma unroll
        for (int off = 16; off > 0; off >>= 1)
            a += __shfl_xor_sync(0xFFFFFFFFu, a, off);
        if (lane == 0) g_nnz[b] = a;
    } else if (wid == 5 && b < 64) {          // pB row b -> g_psum[b]
        float a = g_pB[b * NBLK + lane]      + g_pB[b * NBLK + lane + 32]
                + g_pB[b * NBLK + lane + 64] + g_pB[b * NBLK + lane + 96];
        #pragma unroll
        for (int off = 16; off > 0; off >>= 1)
            a += __shfl_xor_sync(0xFFFFFFFFu, a, off);
        if (lane == 0) g_psum[b] = a;
    } else if (wid == 6 && b == 64) {         // sel -> g_selv
        float a = g_pSel[lane]      + g_pSel[lane + 32]
                + g_pSel[lane + 64] + g_pSel[lane + 96];
        #pragma unroll
        for (int off = 16; off > 0; off >>= 1)
            a += __shfl_xor_sync(0xFFFFFFFFu, a, off);
        if (lane == 0) g_selv = a;
    }
    __syncthreads();

    if (t == 0) g_ncolPart[b] = cs[0] + cs[1];

    // ---- completion ticket: last block finalizes ----
    __shared__ int isLast;
    __threadfence();
    if (t == 0) {
        unsigned int old = atomicAdd(&g_count, 1u);
        isLast = (old == NB3 - 1) ? 1 : 0;
        if (isLast) g_count = 0;              // reset for next graph replay
    }
    __syncthreads();
    if (!isLast) return;
    __threadfence();                           // acquire other blocks' writes

    if (t < 64) out[131104 + t] = g_nnz[t];    // nnz_ch_ba

    if (t < NCH) {
        float m = -1e30f, ns = 0.f, rs = 0.f;
        #pragma unroll
        for (int ba = 0; ba < 8; ba++) {
            float nv = g_nnz[t * 8 + ba];
            m  = fmaxf(m, nv);
            ns += nv;
            rs += g_psum[t * 8 + ba];
        }
        float ncl = 0.f;
        #pragma unroll
        for (int k = 0; k < 16; k++) ncl += g_ncolPart[t * 16 + k];
        out[131072 + t] = m + ncl + rs;        // tot_ch
        out[131080 + t] = m;                   // max_nnz_ch
        out[131088 + t] = ncl;                 // num_col_ch
        out[131096 + t] = rs;                  // num_row_ch
        out[131168 + t] = ns / rs / ncl;       // col_density_ch
    }
    if (t == 0) out[131176] = g_selv;          // num_row_sel
}

// ---------------------------------------------------------------------------
extern "C" void kernel_launch(void* const* d_in, const int* in_sizes, int n_in,
                              void* d_out, int out_size)
{
    const float* W = (const float*)d_in[0];   // [2048, 64]
    const float* D = (const float*)d_in[1];   // [2048, 1024]
    const float* G = (const float*)d_in[2];   // [2048, 64]
    // d_in[3] = i, unused by the math
    float* out = (float*)d_out;

    kf_fused<<<NBLK, 512>>>(W, D, G, out);
    k3_reduce_final<<<NB3, 1024>>>(out);
}